// round 4
// baseline (speedup 1.0000x reference)
#include <cuda_runtime.h>
#include <cuda_bf16.h>
#include <math.h>

#define NT     256
#define VOCAB  256
#define EMPTYE (-(1 << 28))   // exponent sentinel for "group has no mass"

// per-batch partial losses (loss_b / tl_b)
__device__ float g_partial[1024];

// 2^d for d <= 0 (flushes to 0 below -126). d==0 -> 1.0f.
__device__ __forceinline__ float exp2i_neg(int d) {
    return (d < -126) ? 0.f : __int_as_float((127 + d) << 23);
}

// One CTA per batch element. Linear-domain CTC forward scan with
// per-group (4-state) block-floating-point exponents: each group of 4
// extended states keeps an int exponent, so cross-state dynamic range is
// unbounded while arithmetic stays pure fp32 FMA.
__global__ __launch_bounds__(NT, 1) void ctc_scan(
    const float* __restrict__ logp,      // [B, T, VOCAB]
    const int*   __restrict__ targets,   // [B, S]
    const int*   __restrict__ input_len, // [B]
    const int*   __restrict__ target_len,// [B]
    int T, int S)
{
    const int b   = blockIdx.x;
    const int tid = threadIdx.x;
    const float* lp = logp    + (size_t)b * T * VOCAB;
    const int*   tg = targets + (size_t)b * S;
    const int il = input_len[b];
    const int tl = target_len[b];
    const int Lb = 2 * tl + 1;               // number of valid extended states
    const int ng = (Lb + 3) >> 2;            // groups of 4 states

    // alpha mantissas at abuf[buf][4 + s]; [0..3] zero padding for the s-1 halo.
    __shared__ float abuf[2][808];
    __shared__ int   gexp[2][204];           // per-group exponents
    __shared__ float psh[2][VOCAB];          // exp(log_probs[t]) double buffer

    for (int j = tid; j < 808; j += NT) { abuf[0][j] = 0.f; abuf[1][j] = 0.f; }
    for (int j = tid; j < 204; j += NT) { gexp[0][j] = EMPTYE; gexp[1][j] = EMPTYE; }
    __syncthreads();

    // Per-thread static group data: thread i owns states 4i..4i+3.
    // Even states (4i, 4i+2) are BLANK(=1); odd states map to targets[2i], targets[2i+1].
    const int i = tid;
    int tg0 = 0, tg1 = 0;
    float cs0 = 0.f, cs1 = 0.f, m0 = 0.f, m1 = 0.f, m2 = 0.f, m3 = 0.f;
    const bool isg = (i < ng);
    if (isg) {
        int j0 = 2 * i, j1 = 2 * i + 1, jm = 2 * i - 1;
        tg0 = (j0 < S) ? tg[j0] : 0;
        tg1 = (j1 < S) ? tg[j1] : 0;
        int tgm = (jm >= 0) ? tg[jm] : -1;
        cs0 = (tg0 != tgm) ? 1.f : 0.f;      // can_skip for state 4i+1
        cs1 = (tg1 != tg0) ? 1.f : 0.f;      // can_skip for state 4i+3
        int s0 = 4 * i;
        m0 = (s0     < Lb) ? 1.f : 0.f;
        m1 = (s0 + 1 < Lb) ? 1.f : 0.f;
        m2 = (s0 + 2 < Lb) ? 1.f : 0.f;
        m3 = (s0 + 3 < Lb) ? 1.f : 0.f;
    }

    // Prologue: psh[0] = exp(row 1); prefetch rows 2..5 into register queue.
    float q0 = 0.f, q1 = 0.f, q2 = 0.f, q3 = 0.f;
    psh[0][tid] = __expf(lp[(size_t)1 * VOCAB + tid]);
    if (2 < T) q0 = lp[(size_t)2 * VOCAB + tid];
    if (3 < T) q1 = lp[(size_t)3 * VOCAB + tid];
    if (4 < T) q2 = lp[(size_t)4 * VOCAB + tid];
    if (5 < T) q3 = lp[(size_t)5 * VOCAB + tid];
    // alpha_0: states 0 (blank) and 1 (first target); group 0 exponent = 0.
    if (tid == 0) { abuf[0][4] = __expf(lp[1]); gexp[0][0] = 0; }
    if (tid == 1) { abuf[0][5] = __expf(lp[tg[0]]); }
    __syncthreads();

    int cur = 0;

    for (int t = 1; t < il; ++t) {
        const int nxt = cur ^ 1;
        // Build probs for row t+1 (consumed next iteration).
        psh[nxt][tid] = __expf(q0);
        q0 = q1; q1 = q2; q2 = q3;
        {
            int ri = t + 5;
            q3 = (ri < T) ? lp[(size_t)ri * VOCAB + tid] : 0.f;
        }

        // Wavefront: alpha_t[s] can be nonzero only for s <= 2t+1.
        if (isg && 4 * i <= 2 * t + 1) {
            const float* A  = abuf[cur];
            const float* ps = psh[cur];
            float4 a  = *(const float4*)(A + 4 + 4 * i);   // alpha[4i..4i+3]
            float hm  = A[3 + 4 * i];                      // halo: alpha[4i-1]
            int Ei = gexp[cur][i];
            int Em = (i > 0) ? gexp[cur][i - 1] : EMPTYE;
            int Eref = max(Ei, Em);
            float sA = exp2i_neg(Ei - Eref);
            float sH = exp2i_neg(Em - Eref);
            float ax = a.x * sA, ay = a.y * sA, az = a.z * sA, aw = a.w * sA;
            float h  = hm * sH;
            float pb = ps[1];
            float p0 = ps[tg0];
            float p1 = ps[tg1];
            // even states: self + prev; odd states: self + prev + can_skip*prev2
            float n0 = (ax + h) * pb * m0;
            float n1 = (ay + fmaf(cs0, h, ax)) * p0 * m1;
            float n2 = (az + ay) * pb * m2;
            float n3 = (aw + fmaf(cs1, ay, az)) * p1 * m3;
            float gm = fmaxf(fmaxf(n0, n1), fmaxf(n2, n3));
            int newE; float sc;
            if (gm > 0.f) {
                int e = ((__float_as_int(gm) >> 23) & 255) - 127; // ilogb (subnormal->-127, safe)
                newE = Eref + e;
                sc = __int_as_float((127 - e) << 23);             // 2^-e, e in [-127, ~4]
            } else {
                newE = EMPTYE;
                sc = 0.f;
            }
            *(float4*)(abuf[nxt] + 4 + 4 * i) =
                make_float4(n0 * sc, n1 * sc, n2 * sc, n3 * sc);
            gexp[nxt][i] = newE;
        }

        __syncthreads();
        cur = nxt;
    }

    if (tid == 0) {
        const int send = 2 * tl;
        float v1 = abuf[cur][4 + send];       // alpha[2*tl]
        float v0 = abuf[cur][3 + send];       // alpha[2*tl - 1]
        int E1 = gexp[cur][send >> 2];
        int E0 = gexp[cur][(send - 1) >> 2];
        int M = EMPTYE;
        if (v1 > 0.f) M = max(M, E1);
        if (v0 > 0.f) M = max(M, E0);
        float outv = 0.f;
        if (M != EMPTYE) {
            double s = 0.0;
            if (v1 > 0.f) s += ldexp((double)v1, E1 - M);
            if (v0 > 0.f) s += ldexp((double)v0, E0 - M);
            double ll = log(s) + (double)M * 0.6931471805599453;
            double l = -ll;
            if (!(l < 1e29)) l = 0.0;
            outv = (float)(l / (double)tl);
        }
        g_partial[b] = outv;
    }
}

__global__ void ctc_reduce(float* __restrict__ out, int B)
{
    int tid = threadIdx.x;
    float v = 0.f;
    for (int j = tid; j < B; j += 32) v += g_partial[j];
    #pragma unroll
    for (int o = 16; o; o >>= 1) v += __shfl_xor_sync(0xffffffffu, v, o);
    if (tid == 0) out[0] = v / (float)B;
}

extern "C" void kernel_launch(void* const* d_in, const int* in_sizes, int n_in,
                              void* d_out, int out_size)
{
    const float* logp    = (const float*)d_in[0];
    const int*   targets = (const int*)d_in[1];
    const int*   il      = (const int*)d_in[2];
    const int*   tl      = (const int*)d_in[3];
    const int B = in_sizes[2];
    const int S = in_sizes[1] / B;
    const int T = in_sizes[0] / (B * VOCAB);

    ctc_scan<<<B, NT>>>(logp, targets, il, tl, T, S);
    ctc_reduce<<<1, 32>>>((float*)d_out, B);
}

// round 6
// speedup vs baseline: 1.3726x; 1.3726x over previous
#include <cuda_runtime.h>
#include <cuda_bf16.h>
#include <math.h>

#define NT     256
#define VOCAB  256
#define EMPTYE (-(1 << 28))   // exponent sentinel for "group has no mass"

// per-batch partial losses (loss_b / tl_b)
__device__ float g_partial[1024];

// 2^d for d <= 0 (flushes to 0 below -126). d==0 -> 1.0f.
__device__ __forceinline__ float exp2i_neg(int d) {
    return (d < -126) ? 0.f : __int_as_float((127 + d) << 23);
}

// One CTA per batch element. Linear-domain CTC forward scan,
// per-group (4-state) block-floating-point exponents,
// TWO time steps fused per barrier (halo recomputation).
__global__ __launch_bounds__(NT, 1) void ctc_scan(
    const float* __restrict__ logp,      // [B, T, VOCAB]
    const int*   __restrict__ targets,   // [B, S]
    const int*   __restrict__ input_len, // [B]
    const int*   __restrict__ target_len,// [B]
    int T, int S)
{
    const int b   = blockIdx.x;
    const int tid = threadIdx.x;
    const float* lp = logp    + (size_t)b * T * VOCAB;
    const int*   tg = targets + (size_t)b * S;
    const int il = input_len[b];
    const int tl = target_len[b];
    const int Lb = 2 * tl + 1;               // number of valid extended states
    const int ng = (Lb + 3) >> 2;            // groups of 4 states

    // alpha mantissas at abuf[buf][4 + s]; [0..3] zero padding for halo.
    __shared__ float abuf[2][808];
    __shared__ int   gexp[2][204];           // per-group exponents
    __shared__ float psh[2][2][VOCAB];       // exp(log_probs) rows: [pairbuf][0]=t, [1]=t+1

    for (int j = tid; j < 808; j += NT) { abuf[0][j] = 0.f; abuf[1][j] = 0.f; }
    for (int j = tid; j < 204; j += NT) { gexp[0][j] = EMPTYE; gexp[1][j] = EMPTYE; }
    __syncthreads();

    // Thread i owns states 4i..4i+3. Even states are BLANK(=1);
    // odd states 4i+1, 4i+3 map to targets[2i], targets[2i+1].
    // For fusion it also recomputes neighbor state 4i-1 (label targets[2i-1]).
    const int i = tid;
    int tg0 = 0, tg1 = 0, tgm1 = 0;
    float cs0 = 0.f, cs1 = 0.f, csm1 = 0.f;
    float m0 = 0.f, m1 = 0.f, m2 = 0.f, m3 = 0.f, mm1 = 0.f;
    const bool isg = (i < ng);
    if (isg) {
        int j0 = 2 * i, j1 = 2 * i + 1;
        tg0 = (j0 < S) ? tg[j0] : 0;
        tg1 = (j1 < S) ? tg[j1] : 0;
        int tgm  = (i > 0) ? tg[2 * i - 1] : -1;            // label of state 4i-1
        int tgmm = (2 * i - 2 >= 0) ? tg[2 * i - 2] : -1;   // label of state 4i-3
        tgm1 = (i > 0) ? tgm : 0;
        cs0  = (tg0 != tgm)  ? 1.f : 0.f;          // can_skip state 4i+1
        cs1  = (tg1 != tg0)  ? 1.f : 0.f;          // can_skip state 4i+3
        csm1 = (i > 0 && tgm != tgmm) ? 1.f : 0.f; // can_skip state 4i-1
        int s0 = 4 * i;
        m0  = (s0     < Lb) ? 1.f : 0.f;
        m1  = (s0 + 1 < Lb) ? 1.f : 0.f;
        m2  = (s0 + 2 < Lb) ? 1.f : 0.f;
        m3  = (s0 + 3 < Lb) ? 1.f : 0.f;
        mm1 = (i > 0 && s0 - 1 < Lb) ? 1.f : 0.f;  // state 4i-1 validity
    }

    // Prologue: psh[0] = exp(rows 1,2); 6-deep raw prefetch queue rows 3..8.
    float q0 = 0.f, q1 = 0.f, q2 = 0.f, q3 = 0.f, q4 = 0.f, q5 = 0.f;
    if (1 < T) psh[0][0][tid] = __expf(lp[(size_t)1 * VOCAB + tid]);
    if (2 < T) psh[0][1][tid] = __expf(lp[(size_t)2 * VOCAB + tid]);
    if (3 < T) q0 = lp[(size_t)3 * VOCAB + tid];
    if (4 < T) q1 = lp[(size_t)4 * VOCAB + tid];
    if (5 < T) q2 = lp[(size_t)5 * VOCAB + tid];
    if (6 < T) q3 = lp[(size_t)6 * VOCAB + tid];
    if (7 < T) q4 = lp[(size_t)7 * VOCAB + tid];
    if (8 < T) q5 = lp[(size_t)8 * VOCAB + tid];
    // alpha_0: states 0 (blank) and 1 (first target); group 0 exponent = 0.
    if (tid == 0) { abuf[0][4] = __expf(lp[1]); gexp[0][0] = 0; }
    if (tid == 1) { abuf[0][5] = __expf(lp[tg[0]]); }
    __syncthreads();

    int cur = 0, pb = 0;
    int t = 1;

    // Fused loop: each iteration advances steps t and t+1 with ONE barrier.
    for (; t + 1 < il; t += 2) {
        // Stage exp rows t+2, t+3 into the other pair buffer; refill queue.
        psh[pb ^ 1][0][tid] = __expf(q0);
        psh[pb ^ 1][1][tid] = __expf(q1);
        q0 = q2; q1 = q3; q2 = q4; q3 = q5;
        {
            int r0 = t + 8, r1 = t + 9;
            q4 = (r0 < T) ? lp[(size_t)r0 * VOCAB + tid] : 0.f;
            q5 = (r1 < T) ? lp[(size_t)r1 * VOCAB + tid] : 0.f;
        }

        // Wavefront: own states reachable at step t+1 iff 4i <= 2(t+1)+1.
        if (isg && 4 * i <= 2 * t + 3) {
            const float* A   = abuf[cur];
            const float* pst = psh[pb][0];
            const float* psu = psh[pb][1];
            float4 a  = *(const float4*)(A + 4 + 4 * i);   // alpha[4i..4i+3]
            float4 pm = *(const float4*)(A + 4 * i);       // alpha[4i-4..4i-1] (pads for i=0)
            int Ei = gexp[cur][i];
            int Em = (i > 0) ? gexp[cur][i - 1] : EMPTYE;
            int Eref = max(Ei, Em);
            float sA = exp2i_neg(Ei - Eref);
            float sH = exp2i_neg(Em - Eref);
            float ax = a.x * sA, ay = a.y * sA, az = a.z * sA, aw = a.w * sA;
            float h3 = pm.y * sH, h2 = pm.z * sH, h1 = pm.w * sH; // alpha[4i-3,4i-2,4i-1]
            float ptb = pst[1], ptm = pst[tgm1], pt0 = pst[tg0], pt1 = pst[tg1];
            float pub = psu[1], pu0 = psu[tg0], pu1 = psu[tg1];
            // ---- step t (need own 4 states + neighbor state 4i-1) ----
            float b1 = (h1 + fmaf(csm1, h3, h2)) * ptm * mm1;     // state 4i-1
            float c0 = (ax + h1) * ptb * m0;
            float c1 = (ay + fmaf(cs0, h1, ax)) * pt0 * m1;
            float c2 = (az + ay) * ptb * m2;
            float c3 = (aw + fmaf(cs1, ay, az)) * pt1 * m3;
            // ---- step t+1 (own 4 states) ----
            float n0 = (c0 + b1) * pub * m0;
            float n1 = (c1 + fmaf(cs0, b1, c0)) * pu0 * m1;
            float n2 = (c2 + c1) * pub * m2;
            float n3 = (c3 + fmaf(cs1, c1, c2)) * pu1 * m3;
            // ---- renormalize group ----
            float gm = fmaxf(fmaxf(n0, n1), fmaxf(n2, n3));
            int newE; float sc;
            if (gm > 0.f) {
                int e = ((__float_as_int(gm) >> 23) & 255) - 127;
                newE = Eref + e;
                sc = __int_as_float((127 - e) << 23);             // 2^-e
            } else {
                newE = EMPTYE;
                sc = 0.f;
            }
            *(float4*)(abuf[cur ^ 1] + 4 + 4 * i) =
                make_float4(n0 * sc, n1 * sc, n2 * sc, n3 * sc);
            gexp[cur ^ 1][i] = newE;
        }

        __syncthreads();
        cur ^= 1;
        pb ^= 1;
    }

    // Single-step tail if (il - 1) is odd. Row t is in psh[pb][0].
    if (t < il) {
        if (isg && 4 * i <= 2 * t + 1) {
            const float* A   = abuf[cur];
            const float* pst = psh[pb][0];
            float4 a  = *(const float4*)(A + 4 + 4 * i);
            float hm  = A[3 + 4 * i];
            int Ei = gexp[cur][i];
            int Em = (i > 0) ? gexp[cur][i - 1] : EMPTYE;
            int Eref = max(Ei, Em);
            float sA = exp2i_neg(Ei - Eref);
            float sH = exp2i_neg(Em - Eref);
            float ax = a.x * sA, ay = a.y * sA, az = a.z * sA, aw = a.w * sA;
            float h  = hm * sH;
            float ptb = pst[1], pt0 = pst[tg0], pt1 = pst[tg1];
            float n0 = (ax + h) * ptb * m0;
            float n1 = (ay + fmaf(cs0, h, ax)) * pt0 * m1;
            float n2 = (az + ay) * ptb * m2;
            float n3 = (aw + fmaf(cs1, ay, az)) * pt1 * m3;
            float gm = fmaxf(fmaxf(n0, n1), fmaxf(n2, n3));
            int newE; float sc;
            if (gm > 0.f) {
                int e = ((__float_as_int(gm) >> 23) & 255) - 127;
                newE = Eref + e;
                sc = __int_as_float((127 - e) << 23);
            } else {
                newE = EMPTYE;
                sc = 0.f;
            }
            *(float4*)(abuf[cur ^ 1] + 4 + 4 * i) =
                make_float4(n0 * sc, n1 * sc, n2 * sc, n3 * sc);
            gexp[cur ^ 1][i] = newE;
        }
        __syncthreads();
        cur ^= 1;
    }

    if (tid == 0) {
        const int send = 2 * tl;
        float v1 = abuf[cur][4 + send];       // alpha[2*tl]
        float v0 = abuf[cur][3 + send];       // alpha[2*tl - 1]
        int E1 = gexp[cur][send >> 2];
        int E0 = gexp[cur][(send - 1) >> 2];
        int M = EMPTYE;
        if (v1 > 0.f) M = max(M, E1);
        if (v0 > 0.f) M = max(M, E0);
        float outv = 0.f;
        if (M != EMPTYE) {
            double s = 0.0;
            if (v1 > 0.f) s += ldexp((double)v1, E1 - M);
            if (v0 > 0.f) s += ldexp((double)v0, E0 - M);
            double ll = log(s) + (double)M * 0.6931471805599453;
            double l = -ll;
            if (!(l < 1e29)) l = 0.0;
            outv = (float)(l / (double)tl);
        }
        g_partial[b] = outv;
    }
}

__global__ void ctc_reduce(float* __restrict__ out, int B)
{
    int tid = threadIdx.x;
    float v = 0.f;
    for (int j = tid; j < B; j += 32) v += g_partial[j];
    #pragma unroll
    for (int o = 16; o; o >>= 1) v += __shfl_xor_sync(0xffffffffu, v, o);
    if (tid == 0) out[0] = v / (float)B;
}

extern "C" void kernel_launch(void* const* d_in, const int* in_sizes, int n_in,
                              void* d_out, int out_size)
{
    const float* logp    = (const float*)d_in[0];
    const int*   targets = (const int*)d_in[1];
    const int*   il      = (const int*)d_in[2];
    const int*   tl      = (const int*)d_in[3];
    const int B = in_sizes[2];
    const int S = in_sizes[1] / B;
    const int T = in_sizes[0] / (B * VOCAB);

    ctc_scan<<<B, NT>>>(logp, targets, il, tl, T, S);
    ctc_reduce<<<1, 32>>>((float*)d_out, B);
}

// round 8
// speedup vs baseline: 2.0708x; 1.5087x over previous
#include <cuda_runtime.h>
#include <cuda_bf16.h>
#include <math.h>

#define NT     256
#define VOCAB  256
#define EMPTYE (-(1 << 28))   // exponent sentinel for "group has no mass"

// per-batch partial losses (loss_b / tl_b)
__device__ float g_partial[1024];

// 2^d for d <= 0 (flushes to 0 below -126). d==0 -> 1.0f.
__device__ __forceinline__ float exp2i_neg(int d) {
    return (d < -126) ? 0.f : __int_as_float((127 + d) << 23);
}

// One CTA per batch element. Linear-domain CTC forward scan,
// per-group (4-state) block-floating-point exponents,
// FOUR time steps fused per barrier (8-state halo recomputation pyramid).
__global__ __launch_bounds__(NT, 1) void ctc_scan(
    const float* __restrict__ logp,      // [B, T, VOCAB]
    const int*   __restrict__ targets,   // [B, S]
    const int*   __restrict__ input_len, // [B]
    const int*   __restrict__ target_len,// [B]
    int T, int S)
{
    const int b   = blockIdx.x;
    const int tid = threadIdx.x;
    const float* lp = logp    + (size_t)b * T * VOCAB;
    const int*   tg = targets + (size_t)b * S;
    const int il = input_len[b];
    const int tl = target_len[b];
    const int Lb = 2 * tl + 1;               // number of valid extended states
    const int ng = (Lb + 3) >> 2;            // groups of 4 states

    // alpha mantissas at abuf[buf][8 + s]; [0..7] zero padding for the 8-state halo.
    __shared__ float abuf[2][816];
    __shared__ int   gexp[2][204];           // per-group exponents
    __shared__ float psh[2][4][VOCAB];       // exp(log_probs) rows t..t+3, double buffered

    for (int j = tid; j < 816; j += NT) { abuf[0][j] = 0.f; abuf[1][j] = 0.f; }
    for (int j = tid; j < 204; j += NT) { gexp[0][j] = EMPTYE; gexp[1][j] = EMPTYE; }
    __syncthreads();

    // Thread i owns states 4i..4i+3 and recomputes halo states 4i-6..4i-1.
    const int i = tid;
    int lbm3 = 0, lbm2 = 0, lbm1 = 0, lb0 = 0, lb1 = 0;
    float csm3 = 0.f, csm2 = 0.f, csm1 = 0.f, cs0 = 0.f, cs1 = 0.f;
    float m0 = 0.f, m1 = 0.f, m2 = 0.f, m3 = 0.f;
    const bool isg = (i < ng);
    if (isg) {
        // targets tg[2i-4 .. 2i+1], guarded
        int j4 = 2 * i - 4, j3 = 2 * i - 3, j2 = 2 * i - 2, j1m = 2 * i - 1;
        int j0 = 2 * i, j1 = 2 * i + 1;
        int t4 = (j4 >= 0) ? tg[j4] : -1;
        int t3 = (j3 >= 0) ? tg[j3] : -1;
        int t2 = (j2 >= 0) ? tg[j2] : -1;
        int t1m = (j1m >= 0) ? tg[j1m] : -1;
        int t0v = (j0 < S) ? tg[j0] : 0;
        int t1v = (j1 < S) ? tg[j1] : 0;
        lbm3 = (j3 >= 0) ? t3 : 0;
        lbm2 = (j2 >= 0) ? t2 : 0;
        lbm1 = (j1m >= 0) ? t1m : 0;
        lb0 = t0v; lb1 = t1v;
        csm3 = (j3 >= 0 && t3 != t4)  ? 1.f : 0.f;  // state 4i-5
        csm2 = (j2 >= 0 && t2 != t3)  ? 1.f : 0.f;  // state 4i-3
        csm1 = (j1m >= 0 && t1m != t2) ? 1.f : 0.f; // state 4i-1
        cs0  = (t0v != t1m) ? 1.f : 0.f;            // state 4i+1
        cs1  = (t1v != t0v) ? 1.f : 0.f;            // state 4i+3
        int s0 = 4 * i;
        m0 = (s0     < Lb) ? 1.f : 0.f;
        m1 = (s0 + 1 < Lb) ? 1.f : 0.f;
        m2 = (s0 + 2 < Lb) ? 1.f : 0.f;
        m3 = (s0 + 3 < Lb) ? 1.f : 0.f;
    }

    // Prologue: psh[0] = exp(rows 1..4); raw prefetch queue q0..q7 = rows 5..12.
    float q0=0.f,q1=0.f,q2=0.f,q3=0.f,q4=0.f,q5=0.f,q6=0.f,q7=0.f;
    #define RAW(r) (((r) < T) ? lp[(size_t)(r) * VOCAB + tid] : 0.f)
    if (1 < T) psh[0][0][tid] = __expf(lp[(size_t)1 * VOCAB + tid]);
    if (2 < T) psh[0][1][tid] = __expf(lp[(size_t)2 * VOCAB + tid]);
    if (3 < T) psh[0][2][tid] = __expf(lp[(size_t)3 * VOCAB + tid]);
    if (4 < T) psh[0][3][tid] = __expf(lp[(size_t)4 * VOCAB + tid]);
    q0 = RAW(5);  q1 = RAW(6);  q2 = RAW(7);  q3 = RAW(8);
    q4 = RAW(9);  q5 = RAW(10); q6 = RAW(11); q7 = RAW(12);
    // alpha_0: states 0 (blank) and 1 (first target); group 0 exponent = 0.
    if (tid == 0) { abuf[0][8] = __expf(lp[1]); gexp[0][0] = 0; }
    if (tid == 1) { abuf[0][9] = __expf(lp[tg[0]]); }
    __syncthreads();

    int cur = 0, pb = 0;
    int t = 1;

    // Fused loop: each iteration advances steps t..t+3 with ONE barrier.
    for (; t + 3 < il; t += 4) {
        // Stage exp rows t+4..t+7 into the other pair buffer; refill queue.
        psh[pb ^ 1][0][tid] = __expf(q0);
        psh[pb ^ 1][1][tid] = __expf(q1);
        psh[pb ^ 1][2][tid] = __expf(q2);
        psh[pb ^ 1][3][tid] = __expf(q3);
        q0 = q4; q1 = q5; q2 = q6; q3 = q7;
        q4 = RAW(t + 12); q5 = RAW(t + 13); q6 = RAW(t + 14); q7 = RAW(t + 15);

        // Own states reachable at step t+3 iff 4i <= 2(t+3)+1.
        if (isg && 4 * i <= 2 * t + 7) {
            const float* A = abuf[cur];
            float4 pmm = *(const float4*)(A + 4 * i);       // states 4i-8..4i-5
            float4 pm  = *(const float4*)(A + 4 + 4 * i);   // states 4i-4..4i-1
            float4 a   = *(const float4*)(A + 8 + 4 * i);   // states 4i..4i+3
            int Ei  = gexp[cur][i];
            int Em  = (i > 0) ? gexp[cur][i - 1] : EMPTYE;
            int Emm = (i > 1) ? gexp[cur][i - 2] : EMPTYE;
            int Eref = max(Ei, max(Em, Emm));
            float sA  = exp2i_neg(Ei  - Eref);
            float sH  = exp2i_neg(Em  - Eref);
            float sHH = exp2i_neg(Emm - Eref);
            // x_k = state 4i-8+k in base 2^Eref
            float x1 = pmm.y * sHH, x2 = pmm.z * sHH, x3 = pmm.w * sHH;
            float x4 = pm.x * sH,  x5 = pm.y * sH,  x6 = pm.z * sH,  x7 = pm.w * sH;
            float x8 = a.x * sA,   x9 = a.y * sA,   x10 = a.z * sA,  x11 = a.w * sA;

            const float* p0r = psh[pb][0];
            const float* p1r = psh[pb][1];
            const float* p2r = psh[pb][2];
            const float* p3r = psh[pb][3];

            // Layer 1 (row t): states 4i-6..4i+3
            {
                float pbk = p0r[1];
                float pm3 = p0r[lbm3], pm2 = p0r[lbm2], pm1 = p0r[lbm1];
                float pl0 = p0r[lb0],  pl1 = p0r[lb1];
                float y2  = (x2 + x1) * pbk;
                float y3  = (x3 + fmaf(csm3, x1, x2)) * pm3;
                float y4  = (x4 + x3) * pbk;
                float y5  = (x5 + fmaf(csm2, x3, x4)) * pm2;
                float y6  = (x6 + x5) * pbk;
                float y7  = (x7 + fmaf(csm1, x5, x6)) * pm1;
                float y8  = (x8 + x7) * pbk;
                float y9  = (x9 + fmaf(cs0, x7, x8)) * pl0;
                float y10 = (x10 + x9) * pbk;
                float y11 = (x11 + fmaf(cs1, x9, x10)) * pl1;
                (void)y2;
                // Layer 2 (row t+1): states 4i-4..4i+3
                float qbk = p1r[1];
                float qm2 = p1r[lbm2], qm1 = p1r[lbm1];
                float ql0 = p1r[lb0],  ql1 = p1r[lb1];
                float z4  = (y4 + y3) * qbk;
                float z5  = (y5 + fmaf(csm2, y3, y4)) * qm2;
                float z6  = (y6 + y5) * qbk;
                float z7  = (y7 + fmaf(csm1, y5, y6)) * qm1;
                float z8  = (y8 + y7) * qbk;
                float z9  = (y9 + fmaf(cs0, y7, y8)) * ql0;
                float z10 = (y10 + y9) * qbk;
                float z11 = (y11 + fmaf(cs1, y9, y10)) * ql1;
                (void)z4;
                // Layer 3 (row t+2): states 4i-2..4i+3
                float rbk = p2r[1];
                float rm1 = p2r[lbm1], rl0 = p2r[lb0], rl1 = p2r[lb1];
                float w6  = (z6 + z5) * rbk;
                float w7  = (z7 + fmaf(csm1, z5, z6)) * rm1;
                float w8  = (z8 + z7) * rbk;
                float w9  = (z9 + fmaf(cs0, z7, z8)) * rl0;
                float w10 = (z10 + z9) * rbk;
                float w11 = (z11 + fmaf(cs1, z9, z10)) * rl1;
                (void)w6;
                // Layer 4 (row t+3): own 4 states, masked
                float sbk = p3r[1];
                float sl0 = p3r[lb0], sl1 = p3r[lb1];
                float n0 = (w8 + w7) * sbk * m0;
                float n1 = (w9 + fmaf(cs0, w7, w8)) * sl0 * m1;
                float n2 = (w10 + w9) * sbk * m2;
                float n3 = (w11 + fmaf(cs1, w9, w10)) * sl1 * m3;
                // Renormalize group
                float gm = fmaxf(fmaxf(n0, n1), fmaxf(n2, n3));
                int newE; float sc;
                if (gm > 0.f) {
                    int e = ((__float_as_int(gm) >> 23) & 255) - 127;
                    newE = Eref + e;
                    sc = __int_as_float((127 - e) << 23);   // 2^-e
                } else {
                    newE = EMPTYE;
                    sc = 0.f;
                }
                *(float4*)(abuf[cur ^ 1] + 8 + 4 * i) =
                    make_float4(n0 * sc, n1 * sc, n2 * sc, n3 * sc);
                gexp[cur ^ 1][i] = newE;
            }
        }

        __syncthreads();
        cur ^= 1;
        pb ^= 1;
    }

    // Single-step tail (up to 3 steps). Rows t..t+2 live in psh[pb][0..2].
    int st = 0;
    for (; t < il; ++t, ++st) {
        if (isg && 4 * i <= 2 * t + 1) {
            const float* A   = abuf[cur];
            const float* pst = psh[pb][st];
            float4 a  = *(const float4*)(A + 8 + 4 * i);
            float hm  = A[7 + 4 * i];
            int Ei = gexp[cur][i];
            int Em = (i > 0) ? gexp[cur][i - 1] : EMPTYE;
            int Eref = max(Ei, Em);
            float sA = exp2i_neg(Ei - Eref);
            float sH = exp2i_neg(Em - Eref);
            float ax = a.x * sA, ay = a.y * sA, az = a.z * sA, aw = a.w * sA;
            float h  = hm * sH;
            float ptb = pst[1], pt0 = pst[lb0], pt1 = pst[lb1];
            float n0 = (ax + h) * ptb * m0;
            float n1 = (ay + fmaf(cs0, h, ax)) * pt0 * m1;
            float n2 = (az + ay) * ptb * m2;
            float n3 = (aw + fmaf(cs1, ay, az)) * pt1 * m3;
            float gm = fmaxf(fmaxf(n0, n1), fmaxf(n2, n3));
            int newE; float sc;
            if (gm > 0.f) {
                int e = ((__float_as_int(gm) >> 23) & 255) - 127;
                newE = Eref + e;
                sc = __int_as_float((127 - e) << 23);
            } else {
                newE = EMPTYE;
                sc = 0.f;
            }
            *(float4*)(abuf[cur ^ 1] + 8 + 4 * i) =
                make_float4(n0 * sc, n1 * sc, n2 * sc, n3 * sc);
            gexp[cur ^ 1][i] = newE;
        }
        __syncthreads();
        cur ^= 1;
    }

    if (tid == 0) {
        const int send = 2 * tl;
        float v1 = abuf[cur][8 + send];       // alpha[2*tl]
        float v0 = abuf[cur][7 + send];       // alpha[2*tl - 1]
        int E1 = gexp[cur][send >> 2];
        int E0 = gexp[cur][(send - 1) >> 2];
        int M = EMPTYE;
        if (v1 > 0.f) M = max(M, E1);
        if (v0 > 0.f) M = max(M, E0);
        float outv = 0.f;
        if (M != EMPTYE) {
            double s = 0.0;
            if (v1 > 0.f) s += ldexp((double)v1, E1 - M);
            if (v0 > 0.f) s += ldexp((double)v0, E0 - M);
            double ll = log(s) + (double)M * 0.6931471805599453;
            double l = -ll;
            if (!(l < 1e29)) l = 0.0;
            outv = (float)(l / (double)tl);
        }
        g_partial[b] = outv;
    }
}

__global__ void ctc_reduce(float* __restrict__ out, int B)
{
    int tid = threadIdx.x;
    float v = 0.f;
    for (int j = tid; j < B; j += 32) v += g_partial[j];
    #pragma unroll
    for (int o = 16; o; o >>= 1) v += __shfl_xor_sync(0xffffffffu, v, o);
    if (tid == 0) out[0] = v / (float)B;
}

extern "C" void kernel_launch(void* const* d_in, const int* in_sizes, int n_in,
                              void* d_out, int out_size)
{
    const float* logp    = (const float*)d_in[0];
    const int*   targets = (const int*)d_in[1];
    const int*   il      = (const int*)d_in[2];
    const int*   tl      = (const int*)d_in[3];
    const int B = in_sizes[2];
    const int S = in_sizes[1] / B;
    const int T = in_sizes[0] / (B * VOCAB);

    ctc_scan<<<B, NT>>>(logp, targets, il, tl, T, S);
    ctc_reduce<<<1, 32>>>((float*)d_out, B);
}

// round 9
// speedup vs baseline: 2.1339x; 1.0305x over previous
#include <cuda_runtime.h>
#include <cuda_bf16.h>
#include <math.h>

#define NT     256
#define VOCAB  256
#define EMPTYE (-(1 << 28))   // exponent sentinel for "group has no mass"

// per-batch partial losses (loss_b / tl_b)
__device__ float g_partial[1024];

// 2^d for d <= 0 (flushes to 0 below -126). d==0 -> 1.0f.
__device__ __forceinline__ float exp2i_neg(int d) {
    return (d < -126) ? 0.f : __int_as_float((127 + d) << 23);
}

// One CTA per batch element. Linear-domain CTC forward scan,
// per-group (4-state) block-floating-point exponents,
// FOUR time steps fused per barrier (8-state halo recomputation pyramid),
// TIME-TRANSPOSED probability staging: pshT[v] = float4 of rows t..t+3,
// so each label gather is ONE LDS.128 instead of 4 scattered LDS.32.
__global__ __launch_bounds__(NT, 1) void ctc_scan(
    const float* __restrict__ logp,      // [B, T, VOCAB]
    const int*   __restrict__ targets,   // [B, S]
    const int*   __restrict__ input_len, // [B]
    const int*   __restrict__ target_len,// [B]
    int T, int S)
{
    const int b   = blockIdx.x;
    const int tid = threadIdx.x;
    const float* lp = logp    + (size_t)b * T * VOCAB;
    const int*   tg = targets + (size_t)b * S;
    const int il = input_len[b];
    const int tl = target_len[b];
    const int Lb = 2 * tl + 1;               // number of valid extended states
    const int ng = (Lb + 3) >> 2;            // groups of 4 states

    // alpha mantissas at abuf[buf][8 + s]; [0..7] zero padding for the 8-state halo.
    __shared__ float  abuf[2][816];
    __shared__ int    gexp[2][204];          // per-group exponents
    __shared__ float4 pshT[2][VOCAB];        // [buf][v] = exp(logp[t..t+3][v])

    for (int j = tid; j < 816; j += NT) { abuf[0][j] = 0.f; abuf[1][j] = 0.f; }
    for (int j = tid; j < 204; j += NT) { gexp[0][j] = EMPTYE; gexp[1][j] = EMPTYE; }
    __syncthreads();

    // Thread i owns states 4i..4i+3 and recomputes halo states 4i-6..4i-1.
    const int i = tid;
    int lbm3 = 0, lbm2 = 0, lbm1 = 0, lb0 = 0, lb1 = 0;
    float csm3 = 0.f, csm2 = 0.f, csm1 = 0.f, cs0 = 0.f, cs1 = 0.f;
    float m0 = 0.f, m1 = 0.f, m2 = 0.f, m3 = 0.f;
    const bool isg = (i < ng);
    if (isg) {
        // targets tg[2i-4 .. 2i+1], guarded
        int j4 = 2 * i - 4, j3 = 2 * i - 3, j2 = 2 * i - 2, j1m = 2 * i - 1;
        int j0 = 2 * i, j1 = 2 * i + 1;
        int t4 = (j4 >= 0) ? tg[j4] : -1;
        int t3 = (j3 >= 0) ? tg[j3] : -1;
        int t2 = (j2 >= 0) ? tg[j2] : -1;
        int t1m = (j1m >= 0) ? tg[j1m] : -1;
        int t0v = (j0 < S) ? tg[j0] : 0;
        int t1v = (j1 < S) ? tg[j1] : 0;
        lbm3 = (j3 >= 0) ? t3 : 0;
        lbm2 = (j2 >= 0) ? t2 : 0;
        lbm1 = (j1m >= 0) ? t1m : 0;
        lb0 = t0v; lb1 = t1v;
        csm3 = (j3 >= 0 && t3 != t4)  ? 1.f : 0.f;  // state 4i-5
        csm2 = (j2 >= 0 && t2 != t3)  ? 1.f : 0.f;  // state 4i-3
        csm1 = (j1m >= 0 && t1m != t2) ? 1.f : 0.f; // state 4i-1
        cs0  = (t0v != t1m) ? 1.f : 0.f;            // state 4i+1
        cs1  = (t1v != t0v) ? 1.f : 0.f;            // state 4i+3
        int s0 = 4 * i;
        m0 = (s0     < Lb) ? 1.f : 0.f;
        m1 = (s0 + 1 < Lb) ? 1.f : 0.f;
        m2 = (s0 + 2 < Lb) ? 1.f : 0.f;
        m3 = (s0 + 3 < Lb) ? 1.f : 0.f;
    }

    // Prologue: pshT[0][tid] = exp(rows 1..4); raw queue q0..q7 = rows 5..12.
    float q0=0.f,q1=0.f,q2=0.f,q3=0.f,q4=0.f,q5=0.f,q6=0.f,q7=0.f;
    #define RAW(r) (((r) < T) ? lp[(size_t)(r) * VOCAB + tid] : 0.f)
    {
        float e1 = (1 < T) ? __expf(lp[(size_t)1 * VOCAB + tid]) : 0.f;
        float e2 = (2 < T) ? __expf(lp[(size_t)2 * VOCAB + tid]) : 0.f;
        float e3 = (3 < T) ? __expf(lp[(size_t)3 * VOCAB + tid]) : 0.f;
        float e4 = (4 < T) ? __expf(lp[(size_t)4 * VOCAB + tid]) : 0.f;
        pshT[0][tid] = make_float4(e1, e2, e3, e4);
    }
    q0 = RAW(5);  q1 = RAW(6);  q2 = RAW(7);  q3 = RAW(8);
    q4 = RAW(9);  q5 = RAW(10); q6 = RAW(11); q7 = RAW(12);
    // alpha_0: states 0 (blank) and 1 (first target); group 0 exponent = 0.
    if (tid == 0) { abuf[0][8] = __expf(lp[1]); gexp[0][0] = 0; }
    if (tid == 1) { abuf[0][9] = __expf(lp[tg[0]]); }
    __syncthreads();

    int cur = 0, pb = 0;
    int t = 1;

    // Fused loop: each iteration advances steps t..t+3 with ONE barrier.
    for (; t + 3 < il; t += 4) {
        // Stage exp rows t+4..t+7 (one STS.128); refill queue.
        pshT[pb ^ 1][tid] = make_float4(__expf(q0), __expf(q1), __expf(q2), __expf(q3));
        q0 = q4; q1 = q5; q2 = q6; q3 = q7;
        q4 = RAW(t + 12); q5 = RAW(t + 13); q6 = RAW(t + 14); q7 = RAW(t + 15);

        // Own states reachable at step t+3 iff 4i <= 2(t+3)+1.
        if (isg && 4 * i <= 2 * t + 7) {
            const float* A = abuf[cur];
            float4 pmm = *(const float4*)(A + 4 * i);       // states 4i-8..4i-5
            float4 pm  = *(const float4*)(A + 4 + 4 * i);   // states 4i-4..4i-1
            float4 a   = *(const float4*)(A + 8 + 4 * i);   // states 4i..4i+3
            int Ei  = gexp[cur][i];
            int Em  = (i > 0) ? gexp[cur][i - 1] : EMPTYE;
            int Emm = (i > 1) ? gexp[cur][i - 2] : EMPTYE;
            int Eref = max(Ei, max(Em, Emm));
            float sA  = exp2i_neg(Ei  - Eref);
            float sH  = exp2i_neg(Em  - Eref);
            float sHH = exp2i_neg(Emm - Eref);
            // x_k = state 4i-8+k in base 2^Eref
            float x1 = pmm.y * sHH, x2 = pmm.z * sHH, x3 = pmm.w * sHH;
            float x4 = pm.x * sH,  x5 = pm.y * sH,  x6 = pm.z * sH,  x7 = pm.w * sH;
            float x8 = a.x * sA,   x9 = a.y * sA,   x10 = a.z * sA,  x11 = a.w * sA;

            // One LDS.128 per label: all 4 layers' probs at once.
            const float4* P = pshT[pb];
            float4 Pbk = P[1];       // blank (broadcast)
            float4 Pm3 = P[lbm3];
            float4 Pm2 = P[lbm2];
            float4 Pm1 = P[lbm1];
            float4 P0  = P[lb0];
            float4 P1  = P[lb1];

            // Layer 1 (row t): states 4i-6..4i+3
            float y3  = (x3 + fmaf(csm3, x1, x2)) * Pm3.x;
            float y4  = (x4 + x3) * Pbk.x;
            float y5  = (x5 + fmaf(csm2, x3, x4)) * Pm2.x;
            float y6  = (x6 + x5) * Pbk.x;
            float y7  = (x7 + fmaf(csm1, x5, x6)) * Pm1.x;
            float y8  = (x8 + x7) * Pbk.x;
            float y9  = (x9 + fmaf(cs0, x7, x8)) * P0.x;
            float y10 = (x10 + x9) * Pbk.x;
            float y11 = (x11 + fmaf(cs1, x9, x10)) * P1.x;
            // Layer 2 (row t+1): states 4i-4..4i+3
            float z5  = (y5 + fmaf(csm2, y3, y4)) * Pm2.y;
            float z6  = (y6 + y5) * Pbk.y;
            float z7  = (y7 + fmaf(csm1, y5, y6)) * Pm1.y;
            float z8  = (y8 + y7) * Pbk.y;
            float z9  = (y9 + fmaf(cs0, y7, y8)) * P0.y;
            float z10 = (y10 + y9) * Pbk.y;
            float z11 = (y11 + fmaf(cs1, y9, y10)) * P1.y;
            // Layer 3 (row t+2): states 4i-2..4i+3
            float w7  = (z7 + fmaf(csm1, z5, z6)) * Pm1.z;
            float w8  = (z8 + z7) * Pbk.z;
            float w9  = (z9 + fmaf(cs0, z7, z8)) * P0.z;
            float w10 = (z10 + z9) * Pbk.z;
            float w11 = (z11 + fmaf(cs1, z9, z10)) * P1.z;
            // Layer 4 (row t+3): own 4 states, masked
            float n0 = (w8 + w7) * Pbk.w * m0;
            float n1 = (w9 + fmaf(cs0, w7, w8)) * P0.w * m1;
            float n2 = (w10 + w9) * Pbk.w * m2;
            float n3 = (w11 + fmaf(cs1, w9, w10)) * P1.w * m3;
            // Renormalize group
            float gm = fmaxf(fmaxf(n0, n1), fmaxf(n2, n3));
            int newE; float sc;
            if (gm > 0.f) {
                int e = ((__float_as_int(gm) >> 23) & 255) - 127;
                newE = Eref + e;
                sc = __int_as_float((127 - e) << 23);   // 2^-e
            } else {
                newE = EMPTYE;
                sc = 0.f;
            }
            *(float4*)(abuf[cur ^ 1] + 8 + 4 * i) =
                make_float4(n0 * sc, n1 * sc, n2 * sc, n3 * sc);
            gexp[cur ^ 1][i] = newE;
        }

        __syncthreads();
        cur ^= 1;
        pb ^= 1;
    }

    // Single-step tail (up to 3 steps). Rows t..t+2 are components 0..2 of pshT[pb].
    int st = 0;
    for (; t < il; ++t, ++st) {
        if (isg && 4 * i <= 2 * t + 1) {
            const float* A = abuf[cur];
            float4 a  = *(const float4*)(A + 8 + 4 * i);
            float hm  = A[7 + 4 * i];
            int Ei = gexp[cur][i];
            int Em = (i > 0) ? gexp[cur][i - 1] : EMPTYE;
            int Eref = max(Ei, Em);
            float sA = exp2i_neg(Ei - Eref);
            float sH = exp2i_neg(Em - Eref);
            float ax = a.x * sA, ay = a.y * sA, az = a.z * sA, aw = a.w * sA;
            float h  = hm * sH;
            float ptb = ((const float*)&pshT[pb][1])[st];
            float pt0 = ((const float*)&pshT[pb][lb0])[st];
            float pt1 = ((const float*)&pshT[pb][lb1])[st];
            float n0 = (ax + h) * ptb * m0;
            float n1 = (ay + fmaf(cs0, h, ax)) * pt0 * m1;
            float n2 = (az + ay) * ptb * m2;
            float n3 = (aw + fmaf(cs1, ay, az)) * pt1 * m3;
            float gm = fmaxf(fmaxf(n0, n1), fmaxf(n2, n3));
            int newE; float sc;
            if (gm > 0.f) {
                int e = ((__float_as_int(gm) >> 23) & 255) - 127;
                newE = Eref + e;
                sc = __int_as_float((127 - e) << 23);
            } else {
                newE = EMPTYE;
                sc = 0.f;
            }
            *(float4*)(abuf[cur ^ 1] + 8 + 4 * i) =
                make_float4(n0 * sc, n1 * sc, n2 * sc, n3 * sc);
            gexp[cur ^ 1][i] = newE;
        }
        __syncthreads();
        cur ^= 1;
    }

    if (tid == 0) {
        const int send = 2 * tl;
        float v1 = abuf[cur][8 + send];       // alpha[2*tl]
        float v0 = abuf[cur][7 + send];       // alpha[2*tl - 1]
        int E1 = gexp[cur][send >> 2];
        int E0 = gexp[cur][(send - 1) >> 2];
        int M = EMPTYE;
        if (v1 > 0.f) M = max(M, E1);
        if (v0 > 0.f) M = max(M, E0);
        float outv = 0.f;
        if (M != EMPTYE) {
            double s = 0.0;
            if (v1 > 0.f) s += ldexp((double)v1, E1 - M);
            if (v0 > 0.f) s += ldexp((double)v0, E0 - M);
            double ll = log(s) + (double)M * 0.6931471805599453;
            double l = -ll;
            if (!(l < 1e29)) l = 0.0;
            outv = (float)(l / (double)tl);
        }
        g_partial[b] = outv;
    }
}

__global__ void ctc_reduce(float* __restrict__ out, int B)
{
    int tid = threadIdx.x;
    float v = 0.f;
    for (int j = tid; j < B; j += 32) v += g_partial[j];
    #pragma unroll
    for (int o = 16; o; o >>= 1) v += __shfl_xor_sync(0xffffffffu, v, o);
    if (tid == 0) out[0] = v / (float)B;
}

extern "C" void kernel_launch(void* const* d_in, const int* in_sizes, int n_in,
                              void* d_out, int out_size)
{
    const float* logp    = (const float*)d_in[0];
    const int*   targets = (const int*)d_in[1];
    const int*   il      = (const int*)d_in[2];
    const int*   tl      = (const int*)d_in[3];
    const int B = in_sizes[2];
    const int S = in_sizes[1] / B;
    const int T = in_sizes[0] / (B * VOCAB);

    ctc_scan<<<B, NT>>>(logp, targets, il, tl, T, S);
    ctc_reduce<<<1, 32>>>((float*)d_out, B);
}

// round 10
// speedup vs baseline: 2.5602x; 1.1998x over previous
#include <cuda_runtime.h>
#include <cuda_bf16.h>
#include <math.h>

#define NT     256
#define VOCAB  256
#define EMPTYE (-(1 << 28))   // exponent sentinel for "group has no mass"

// per-batch partial losses (loss_b / tl_b)
__device__ float g_partial[1024];

// 2^d for d <= 0 (flushes to 0 below -126). d==0 -> 1.0f.
__device__ __forceinline__ float exp2i_neg(int d) {
    return (d < -126) ? 0.f : __int_as_float((127 + d) << 23);
}

// Constant-index float4 component access (folds under full unroll).
__device__ __forceinline__ float f4c(float4 v, int c) {
    switch (c & 3) {
        case 0:  return v.x;
        case 1:  return v.y;
        case 2:  return v.z;
        default: return v.w;
    }
}

// One CTA per batch element. Linear-domain CTC forward scan,
// per-group (4-state) block-floating-point exponents,
// EIGHT time steps fused per barrier (16-state halo pyramid, in registers),
// time-transposed probability staging (pshA: rows t..t+3, pshB: rows t+4..t+7).
__global__ __launch_bounds__(NT, 1) void ctc_scan(
    const float* __restrict__ logp,      // [B, T, VOCAB]
    const int*   __restrict__ targets,   // [B, S]
    const int*   __restrict__ input_len, // [B]
    const int*   __restrict__ target_len,// [B]
    int T, int S)
{
    const int b   = blockIdx.x;
    const int tid = threadIdx.x;
    const float* lp = logp    + (size_t)b * T * VOCAB;
    const int*   tg = targets + (size_t)b * S;
    const int il = input_len[b];
    const int tl = target_len[b];
    const int Lb = 2 * tl + 1;               // number of valid extended states
    const int ng = (Lb + 3) >> 2;            // groups of 4 states

    // alpha mantissas at abuf[buf][16 + s]; [0..15] zero padding for the halo.
    __shared__ float  abuf[2][824];
    __shared__ int    gexp[2][204];          // per-group exponents
    __shared__ float4 pshA[2][VOCAB];        // [buf][v] = exp(logp[t..t+3][v])
    __shared__ float4 pshB[2][VOCAB];        // [buf][v] = exp(logp[t+4..t+7][v])

    for (int j = tid; j < 824; j += NT) { abuf[0][j] = 0.f; abuf[1][j] = 0.f; }
    for (int j = tid; j < 204; j += NT) { gexp[0][j] = EMPTYE; gexp[1][j] = EMPTYE; }
    __syncthreads();

    // Thread i owns states 4i..4i+3; pyramid spans states 4i-16..4i+3 (k=0..19).
    // Odd k=2m+1 -> state 4i-16+k has label tg[2i-8+m], m=0..9.
    const int i = tid;
    int   lbl[10];
    float csv[10];
    float m0 = 0.f, m1 = 0.f, m2 = 0.f, m3 = 0.f;
    const bool isg = (i < ng);
    #pragma unroll
    for (int m = 0; m < 10; ++m) { lbl[m] = 0; csv[m] = 0.f; }
    if (isg) {
        #pragma unroll
        for (int m = 0; m < 10; ++m) {
            int j = 2 * i - 8 + m;
            int lj  = (j >= 0 && j < S) ? tg[j] : 0;
            int ljm = (j - 1 >= 0 && j - 1 < S) ? tg[j - 1] : -1;
            lbl[m] = lj;
            csv[m] = (j >= 1 && lj != ljm) ? 1.f : 0.f;
        }
        int s0 = 4 * i;
        m0 = (s0     < Lb) ? 1.f : 0.f;
        m1 = (s0 + 1 < Lb) ? 1.f : 0.f;
        m2 = (s0 + 2 < Lb) ? 1.f : 0.f;
        m3 = (s0 + 3 < Lb) ? 1.f : 0.f;
    }

    #define RAW(r) (((r) < T) ? lp[(size_t)(r) * VOCAB + tid] : 0.f)
    #define EXPG(r) (((r) < T) ? __expf(lp[(size_t)(r) * VOCAB + tid]) : 0.f)
    // Prologue: stage exp rows 1..8; raw queue q0..q7 = rows 9..16.
    pshA[0][tid] = make_float4(EXPG(1), EXPG(2), EXPG(3), EXPG(4));
    pshB[0][tid] = make_float4(EXPG(5), EXPG(6), EXPG(7), EXPG(8));
    float q0 = RAW(9),  q1 = RAW(10), q2 = RAW(11), q3 = RAW(12);
    float q4 = RAW(13), q5 = RAW(14), q6 = RAW(15), q7 = RAW(16);
    // alpha_0: states 0 (blank) and 1 (first target); group 0 exponent = 0.
    if (tid == 0) { abuf[0][16] = __expf(lp[1]); gexp[0][0] = 0; }
    if (tid == 1) { abuf[0][17] = __expf(lp[tg[0]]); }
    __syncthreads();

    int cur = 0, pb = 0;
    int t = 1;

    // Fused loop: each iteration advances steps t..t+7 with ONE barrier.
    for (; t + 7 < il; t += 8) {
        // Stage exp rows t+8..t+15; refill queue with rows t+16..t+23.
        pshA[pb ^ 1][tid] = make_float4(__expf(q0), __expf(q1), __expf(q2), __expf(q3));
        pshB[pb ^ 1][tid] = make_float4(__expf(q4), __expf(q5), __expf(q6), __expf(q7));
        q0 = RAW(t + 16); q1 = RAW(t + 17); q2 = RAW(t + 18); q3 = RAW(t + 19);
        q4 = RAW(t + 20); q5 = RAW(t + 21); q6 = RAW(t + 22); q7 = RAW(t + 23);

        // Own states reachable at step t+7 iff 4i <= 2(t+7)+1.
        if (isg && 4 * i <= 2 * t + 15) {
            const float* A = abuf[cur];
            float4 g0 = *(const float4*)(A +      4 * i);   // k 0..3   (states 4i-16..)
            float4 g1 = *(const float4*)(A +  4 + 4 * i);   // k 4..7
            float4 g2 = *(const float4*)(A +  8 + 4 * i);   // k 8..11
            float4 g3 = *(const float4*)(A + 12 + 4 * i);   // k 12..15
            float4 g4 = *(const float4*)(A + 16 + 4 * i);   // k 16..19 (own)
            int E0 = (i > 3) ? gexp[cur][i - 4] : EMPTYE;
            int E1 = (i > 2) ? gexp[cur][i - 3] : EMPTYE;
            int E2 = (i > 1) ? gexp[cur][i - 2] : EMPTYE;
            int E3 = (i > 0) ? gexp[cur][i - 1] : EMPTYE;
            int E4 = gexp[cur][i];
            int Eref = max(max(max(E0, E1), max(E2, E3)), E4);
            float s0 = exp2i_neg(E0 - Eref);
            float s1 = exp2i_neg(E1 - Eref);
            float s2 = exp2i_neg(E2 - Eref);
            float s3 = exp2i_neg(E3 - Eref);
            float s4 = exp2i_neg(E4 - Eref);

            float xs[20];
            xs[0]=g0.x*s0;  xs[1]=g0.y*s0;  xs[2]=g0.z*s0;  xs[3]=g0.w*s0;
            xs[4]=g1.x*s1;  xs[5]=g1.y*s1;  xs[6]=g1.z*s1;  xs[7]=g1.w*s1;
            xs[8]=g2.x*s2;  xs[9]=g2.y*s2;  xs[10]=g2.z*s2; xs[11]=g2.w*s2;
            xs[12]=g3.x*s3; xs[13]=g3.y*s3; xs[14]=g3.z*s3; xs[15]=g3.w*s3;
            xs[16]=g4.x*s4; xs[17]=g4.y*s4; xs[18]=g4.z*s4; xs[19]=g4.w*s4;

            const float4* PA = pshA[pb];
            const float4* PB = pshB[pb];
            float4 BKlo = PA[1];
            float4 BKhi = PB[1];
            float4 Plo[10], Phi[10];
            #pragma unroll
            for (int m = 1; m < 10; ++m) Plo[m] = PA[lbl[m]];
            #pragma unroll
            for (int m = 5; m < 10; ++m) Phi[m] = PB[lbl[m]];

            // 8 layers; layer j computes k = 2j..19 in DESCENDING k (in-place).
            #pragma unroll
            for (int j = 1; j <= 8; ++j) {
                float pbj = (j <= 4) ? f4c(BKlo, j - 1) : f4c(BKhi, j - 5);
                #pragma unroll
                for (int k = 19; k >= 2 * j; --k) {
                    if ((k & 1) == 0) {
                        xs[k] = (xs[k] + xs[k - 1]) * pbj;
                    } else {
                        const int m = (k - 1) >> 1;
                        float pl = (j <= 4) ? f4c(Plo[m], j - 1) : f4c(Phi[m], j - 5);
                        xs[k] = (xs[k] + xs[k - 1] + csv[m] * xs[k - 2]) * pl;
                    }
                }
            }

            // Mask own 4 outputs, renormalize group, store.
            float n0 = xs[16] * m0, n1 = xs[17] * m1, n2 = xs[18] * m2, n3 = xs[19] * m3;
            float gm = fmaxf(fmaxf(n0, n1), fmaxf(n2, n3));
            int newE; float sc;
            if (gm > 0.f) {
                int e = ((__float_as_int(gm) >> 23) & 255) - 127;
                newE = Eref + e;
                sc = __int_as_float((127 - e) << 23);   // 2^-e
            } else {
                newE = EMPTYE;
                sc = 0.f;
            }
            *(float4*)(abuf[cur ^ 1] + 16 + 4 * i) =
                make_float4(n0 * sc, n1 * sc, n2 * sc, n3 * sc);
            gexp[cur ^ 1][i] = newE;
        }

        __syncthreads();
        cur ^= 1;
        pb ^= 1;
    }

    // Single-step tail (up to 7 steps). Row t+st: component st of pshA (st<4)
    // or component st-4 of pshB.
    int st = 0;
    for (; t < il; ++t, ++st) {
        if (isg && 4 * i <= 2 * t + 1) {
            const float* A = abuf[cur];
            float4 a  = *(const float4*)(A + 16 + 4 * i);
            float hm  = A[15 + 4 * i];
            int Ei = gexp[cur][i];
            int Em = (i > 0) ? gexp[cur][i - 1] : EMPTYE;
            int Eref = max(Ei, Em);
            float sA = exp2i_neg(Ei - Eref);
            float sH = exp2i_neg(Em - Eref);
            float ax = a.x * sA, ay = a.y * sA, az = a.z * sA, aw = a.w * sA;
            float h  = hm * sH;
            float ptb, pt0, pt1;
            if (st < 4) {
                ptb = f4c(pshA[pb][1],      st);
                pt0 = f4c(pshA[pb][lbl[8]], st);
                pt1 = f4c(pshA[pb][lbl[9]], st);
            } else {
                ptb = f4c(pshB[pb][1],      st - 4);
                pt0 = f4c(pshB[pb][lbl[8]], st - 4);
                pt1 = f4c(pshB[pb][lbl[9]], st - 4);
            }
            float cs0 = csv[8], cs1 = csv[9];
            float n0 = (ax + h) * ptb * m0;
            float n1 = (ay + fmaf(cs0, h, ax)) * pt0 * m1;
            float n2 = (az + ay) * ptb * m2;
            float n3 = (aw + fmaf(cs1, ay, az)) * pt1 * m3;
            float gm = fmaxf(fmaxf(n0, n1), fmaxf(n2, n3));
            int newE; float sc;
            if (gm > 0.f) {
                int e = ((__float_as_int(gm) >> 23) & 255) - 127;
                newE = Eref + e;
                sc = __int_as_float((127 - e) << 23);
            } else {
                newE = EMPTYE;
                sc = 0.f;
            }
            *(float4*)(abuf[cur ^ 1] + 16 + 4 * i) =
                make_float4(n0 * sc, n1 * sc, n2 * sc, n3 * sc);
            gexp[cur ^ 1][i] = newE;
        }
        __syncthreads();
        cur ^= 1;
    }

    if (tid == 0) {
        const int send = 2 * tl;
        float v1 = abuf[cur][16 + send];      // alpha[2*tl]
        float v0 = abuf[cur][15 + send];      // alpha[2*tl - 1]
        int E1 = gexp[cur][send >> 2];
        int E0 = gexp[cur][(send - 1) >> 2];
        int M = EMPTYE;
        if (v1 > 0.f) M = max(M, E1);
        if (v0 > 0.f) M = max(M, E0);
        float outv = 0.f;
        if (M != EMPTYE) {
            double s = 0.0;
            if (v1 > 0.f) s += ldexp((double)v1, E1 - M);
            if (v0 > 0.f) s += ldexp((double)v0, E0 - M);
            double ll = log(s) + (double)M * 0.6931471805599453;
            double l = -ll;
            if (!(l < 1e29)) l = 0.0;
            outv = (float)(l / (double)tl);
        }
        g_partial[b] = outv;
    }
}

__global__ void ctc_reduce(float* __restrict__ out, int B)
{
    int tid = threadIdx.x;
    float v = 0.f;
    for (int j = tid; j < B; j += 32) v += g_partial[j];
    #pragma unroll
    for (int o = 16; o; o >>= 1) v += __shfl_xor_sync(0xffffffffu, v, o);
    if (tid == 0) out[0] = v / (float)B;
}

extern "C" void kernel_launch(void* const* d_in, const int* in_sizes, int n_in,
                              void* d_out, int out_size)
{
    const float* logp    = (const float*)d_in[0];
    const int*   targets = (const int*)d_in[1];
    const int*   il      = (const int*)d_in[2];
    const int*   tl      = (const int*)d_in[3];
    const int B = in_sizes[2];
    const int S = in_sizes[1] / B;
    const int T = in_sizes[0] / (B * VOCAB);

    ctc_scan<<<B, NT>>>(logp, targets, il, tl, T, S);
    ctc_reduce<<<1, 32>>>((float*)d_out, B);
}